// round 2
// baseline (speedup 1.0000x reference)
#include <cuda_runtime.h>
#include <cuda_bf16.h>

// SoftPerspectiveShader: fused sample_textures + softmax_rgb_blend
// Shapes: pix_to_face [N,H,W,K] i32, bary [N,H,W,K,3] f32, zbuf/dists [N,H,W,K] f32,
//         face_colors [F,3,3] f32, out [N,H,W,4] f32.  N=4,H=512,W=512,K=8.
//
// Optimization: with GAMMA=1e-4 and zbuf sorted, exp((z_inv - z_inv_max)/GAMMA)
// underflows to 0 for all but (almost always) one fragment. We therefore only
// touch bary_coords (96MB, the largest input) and the face_colors gather for
// fragments with w > 0 — exact, since w==0 contributes nothing to the blend.

#define SIGMA_F 1e-4f
#define GAMMA_F 1e-4f
#define ZNEAR_F 1.0f
#define ZFAR_F  100.0f
#define EPS_F   1e-10f

__global__ __launch_bounds__(256) void soft_shader_kernel(
    const int4*   __restrict__ p2f,    // [P][2] int4  (K=8)
    const float*  __restrict__ bary,   // [P][8][3]
    const float4* __restrict__ zbuf,   // [P][2] float4
    const float4* __restrict__ dists,  // [P][2] float4
    const float*  __restrict__ fcol,   // [F][3][3]
    float4*       __restrict__ out,    // [P]
    int P)
{
    int p = blockIdx.x * blockDim.x + threadIdx.x;
    if (p >= P) return;

    const int4   fa = p2f[2 * p],   fb = p2f[2 * p + 1];
    const float4 za = zbuf[2 * p],  zb = zbuf[2 * p + 1];
    const float4 da = dists[2 * p], db = dists[2 * p + 1];

    int   faces[8] = {fa.x, fa.y, fa.z, fa.w, fb.x, fb.y, fb.z, fb.w};
    float zv[8]    = {za.x, za.y, za.z, za.w, zb.x, zb.y, zb.z, zb.w};
    float dv[8]    = {da.x, da.y, da.z, da.w, db.x, db.y, db.z, db.w};

    float prob[8], zinv[8];
    float zmax = EPS_F;      // z_inv_max = max(max_k z_inv, EPS)
    float keep = 1.0f;       // prod(1 - prob) = 1 - alpha

#pragma unroll
    for (int k = 0; k < 8; k++) {
        bool  m  = faces[k] >= 0;
        // sigmoid(-d/sigma) = 1/(1+exp(d/sigma)); overflow -> inf -> 0, matches jax stable sigmoid
        float pr = m ? (1.0f / (1.0f + expf(dv[k] / SIGMA_F))) : 0.0f;
        prob[k] = pr;
        keep *= (1.0f - pr);
        float zi = m ? ((ZFAR_F - zv[k]) / (ZFAR_F - ZNEAR_F)) : 0.0f;
        zinv[k] = zi;
        zmax = fmaxf(zmax, zi);
    }

    float delta = fmaxf(expf((EPS_F - zmax) / GAMMA_F), EPS_F);
    float denom = delta;
    float r = 0.0f, g = 0.0f, b = 0.0f;

#pragma unroll
    for (int k = 0; k < 8; k++) {
        float w = prob[k] * expf((zinv[k] - zmax) / GAMMA_F);
        denom += w;
        if (w > 0.0f) {
            // w > 0 implies prob > 0 implies faces[k] >= 0
            const float* bc = bary + (size_t)p * 24 + (size_t)k * 3;
            float b0 = bc[0], b1 = bc[1], b2 = bc[2];
            const float* fc = fcol + (size_t)faces[k] * 9;
            float t0 = b0 * fc[0] + b1 * fc[3] + b2 * fc[6];
            float t1 = b0 * fc[1] + b1 * fc[4] + b2 * fc[7];
            float t2 = b0 * fc[2] + b1 * fc[5] + b2 * fc[8];
            r += w * t0;
            g += w * t1;
            b += w * t2;
        }
    }

    float inv = 1.0f / denom;
    float4 o;
    o.x = (r + delta) * inv;   // background = (1,1,1): + delta*1/denom
    o.y = (g + delta) * inv;
    o.z = (b + delta) * inv;
    o.w = keep;                // 1 - alpha
    out[p] = o;
}

extern "C" void kernel_launch(void* const* d_in, const int* in_sizes, int n_in,
                              void* d_out, int out_size) {
    const int*   p2f   = (const int*)d_in[0];
    const float* bary  = (const float*)d_in[1];
    const float* zbufp = (const float*)d_in[2];
    const float* dist  = (const float*)d_in[3];
    const float* fcol  = (const float*)d_in[4];
    int P = in_sizes[0] / 8;   // N*H*W pixels

    int threads = 256;
    int blocks  = (P + threads - 1) / threads;
    soft_shader_kernel<<<blocks, threads>>>(
        (const int4*)p2f, bary, (const float4*)zbufp, (const float4*)dist,
        fcol, (float4*)d_out, P);
}